// round 3
// baseline (speedup 1.0000x reference)
#include <cuda_runtime.h>
#include <cuda_bf16.h>
#include <cstdint>

// Problem constants (fixed by setup_inputs)
#define BATCH 64
#define CDIM  256
#define NPTS  1024
#define NQ    (BATCH * NPTS)        // 65536 queries
#define KOUT  9

// Scratch: d2 matrix (64 x 1024 x 1024 fp32 = 256MB) + squared norms.
__device__ float g_d2[(size_t)BATCH * NPTS * NPTS];
__device__ float g_sq[NQ];

// ---------------------------------------------------------------------------
// Kernel 1: squared norms  sq[b*N+n] = sum_c x[b,c,n]^2
// x layout: (B, C, N) -> x[b*C*N + c*N + n]
// ---------------------------------------------------------------------------
__global__ void sqnorm_kernel(const float* __restrict__ x) {
    int g = blockIdx.x * blockDim.x + threadIdx.x;   // 0..65535
    int b = g >> 10;
    int n = g & (NPTS - 1);
    const float* xb = x + (size_t)b * CDIM * NPTS + n;
    float s = 0.0f;
    #pragma unroll 8
    for (int c = 0; c < CDIM; c++) {
        float v = xb[(size_t)c * NPTS];
        s = fmaf(v, v, s);
    }
    g_sq[g] = s;
}

// ---------------------------------------------------------------------------
// Kernel 2: batched symmetric GEMM -> d2
// Per batch: G = X^T X (X is C x N, column n = point n's features).
// d2[n,m] = sq[n] + sq[m] - 2 G[n,m].
// CTA computes one 128x128 tile; only upper-triangular tile pairs (ti<=tj),
// mirrored tile written for ti<tj.
// ---------------------------------------------------------------------------
#define BM 128
#define BK 16

__global__ void __launch_bounds__(256, 2) gemm_d2_kernel(const float* __restrict__ x) {
    int b = blockIdx.y;
    int p = blockIdx.x;          // 0..35 upper-tri tile pair
    int ti = 0, tj = 0;
    {
        int acc = 0;
        #pragma unroll
        for (int i = 0; i < 8; i++) {
            int cnt = 8 - i;
            if (p < acc + cnt) { ti = i; tj = i + (p - acc); break; }
            acc += cnt;
        }
    }

    const float* xb = x + (size_t)b * CDIM * NPTS;

    __shared__ float As[BK][BM];
    __shared__ float Bs[BK][BM];

    int tid = threadIdx.x;       // 256 threads
    int tx = tid & 15;
    int ty = tid >> 4;

    int rowbase = ti * BM;
    int colbase = tj * BM;

    float acc[8][8];
    #pragma unroll
    for (int i = 0; i < 8; i++)
        #pragma unroll
        for (int j = 0; j < 8; j++) acc[i][j] = 0.0f;

    for (int k0 = 0; k0 < CDIM; k0 += BK) {
        #pragma unroll
        for (int it = 0; it < 2; it++) {
            int slot = tid + it * 256;          // 0..511 float4 slots
            int kk = slot >> 5;                 // 0..15
            int c4 = (slot & 31) << 2;          // 0..124
            const float* src = xb + (size_t)(k0 + kk) * NPTS;
            float4 va = *(const float4*)(src + rowbase + c4);
            *(float4*)&As[kk][c4] = va;
            float4 vb = *(const float4*)(src + colbase + c4);
            *(float4*)&Bs[kk][c4] = vb;
        }
        __syncthreads();

        #pragma unroll
        for (int kk = 0; kk < BK; kk++) {
            float ra[8], rb[8];
            #pragma unroll
            for (int i = 0; i < 8; i++) ra[i] = As[kk][ty * 8 + i];
            #pragma unroll
            for (int j = 0; j < 8; j++) rb[j] = Bs[kk][tx * 8 + j];
            #pragma unroll
            for (int i = 0; i < 8; i++)
                #pragma unroll
                for (int j = 0; j < 8; j++)
                    acc[i][j] = fmaf(ra[i], rb[j], acc[i][j]);
        }
        __syncthreads();
    }

    float* dbase = g_d2 + ((size_t)b << 20);
    const float* sqb = g_sq + (b << 10);

    float sqr[8], sqc[8];
    #pragma unroll
    for (int i = 0; i < 8; i++) sqr[i] = sqb[rowbase + ty * 8 + i];
    #pragma unroll
    for (int j = 0; j < 8; j++) sqc[j] = sqb[colbase + tx * 8 + j];

    float d2v[8][8];
    #pragma unroll
    for (int i = 0; i < 8; i++)
        #pragma unroll
        for (int j = 0; j < 8; j++)
            d2v[i][j] = sqr[i] + sqc[j] - 2.0f * acc[i][j];

    #pragma unroll
    for (int i = 0; i < 8; i++) {
        int r = rowbase + ty * 8 + i;
        float* dst = dbase + (size_t)r * NPTS + colbase + tx * 8;
        *(float4*)(dst)     = make_float4(d2v[i][0], d2v[i][1], d2v[i][2], d2v[i][3]);
        *(float4*)(dst + 4) = make_float4(d2v[i][4], d2v[i][5], d2v[i][6], d2v[i][7]);
    }

    if (ti != tj) {
        #pragma unroll
        for (int j = 0; j < 8; j++) {
            int c = colbase + tx * 8 + j;
            float* dst = dbase + (size_t)c * NPTS + rowbase + ty * 8;
            *(float4*)(dst)     = make_float4(d2v[0][j], d2v[1][j], d2v[2][j], d2v[3][j]);
            *(float4*)(dst + 4) = make_float4(d2v[4][j], d2v[5][j], d2v[6][j], d2v[7][j]);
        }
    }
}

// ---------------------------------------------------------------------------
// Kernel 3: per-query top-(8*dilation+1) selection, one warp per query.
// Ascending d2, ties -> smaller index (matches jax top_k(-d2) semantics).
// Emit ranks {0, d, 2d, ..., 8d}: src = b*N + m, dst = q.
// OUTPUT IS WRITTEN AS FLOAT32 (harness output dtype) — all values < 2^24,
// exactly representable.
// ---------------------------------------------------------------------------
__global__ void select_knn_kernel(const int* __restrict__ layer_idx,
                                  float* __restrict__ out, int half) {
    int warp = (blockIdx.x * blockDim.x + threadIdx.x) >> 5;
    int lane = threadIdx.x & 31;
    if (warp >= NQ) return;

    // robust dilation: clamp to [1, 3]
    int li = layer_idx[0];
    int dil = li / 4 + 1;
    if (dil > 3) dil = 3;
    if (dil < 1) dil = 1;
    int iters = 8 * dil + 1;

    const float* row = g_d2 + ((size_t)warp << 10);

    // each lane holds 32 candidates; slot s=i*4+j  -> m = i*128 + lane*4 + j
    float v[32];
    #pragma unroll
    for (int i = 0; i < 8; i++) {
        float4 t = *(const float4*)(row + i * 128 + lane * 4);
        v[i * 4 + 0] = t.x; v[i * 4 + 1] = t.y;
        v[i * 4 + 2] = t.z; v[i * 4 + 3] = t.w;
    }

    // lane-local best (slot order is ascending m, strict < keeps smallest m)
    float bv = v[0];
    int bs = 0;
    #pragma unroll
    for (int s = 1; s < 32; s++) {
        if (v[s] < bv) { bv = v[s]; bs = s; }
    }

    int b = warp >> 10;
    int outbase = warp * KOUT;

    for (int r = 0; r < iters; r++) {
        float wv = bv;
        int wm = ((bs >> 2) << 7) + (lane << 2) + (bs & 3);
        #pragma unroll
        for (int o = 16; o > 0; o >>= 1) {
            float ov = __shfl_xor_sync(0xffffffffu, wv, o);
            int om = __shfl_xor_sync(0xffffffffu, wm, o);
            if (ov < wv || (ov == wv && om < wm)) { wv = ov; wm = om; }
        }

        if ((r % dil) == 0 && lane == 0) {
            int oi = outbase + r / dil;
            if (oi < half) {
                out[oi] = (float)((b << 10) + wm);   // src (global neighbor idx)
                out[half + oi] = (float)warp;        // dst (query idx)
            }
        }

        // remove winner from owner lane and rescan its 32 slots
        int owner = (wm >> 2) & 31;
        if (lane == owner) {
            int s = ((wm >> 7) << 2) + (wm & 3);
            #pragma unroll
            for (int ss = 0; ss < 32; ss++)
                if (ss == s) v[ss] = 1e30f;
            bv = v[0]; bs = 0;
            #pragma unroll
            for (int ss = 1; ss < 32; ss++) {
                if (v[ss] < bv) { bv = v[ss]; bs = ss; }
            }
        }
    }
}

// ---------------------------------------------------------------------------
// Launch — identify inputs BY SIZE, not by position:
//   x:         64*256*1024 = 16,777,216 elements
//   layer_idx: 1 element
// ---------------------------------------------------------------------------
extern "C" void kernel_launch(void* const* d_in, const int* in_sizes, int n_in,
                              void* d_out, int out_size) {
    int xi = 0, li = 1;
    if (n_in >= 2) {
        if (in_sizes[0] >= in_sizes[1]) { xi = 0; li = 1; }
        else                            { xi = 1; li = 0; }
    } else {
        xi = 0; li = 0;
    }

    const float* x = (const float*)d_in[xi];
    const int* layer_idx = (const int*)d_in[li];
    float* out = (float*)d_out;
    int half = out_size / 2;   // 589824

    sqnorm_kernel<<<NQ / 256, 256>>>(x);

    dim3 g(36, BATCH);
    gemm_d2_kernel<<<g, 256>>>(x);

    // one warp per query: 65536 warps, 8 warps per block
    select_knn_kernel<<<NQ / 8, 256>>>(layer_idx, out, half);
}

// round 5
// speedup vs baseline: 1.3358x; 1.3358x over previous
#include <cuda_runtime.h>
#include <cuda_bf16.h>
#include <cstdint>

// Problem constants (fixed by setup_inputs)
#define BATCH 64
#define CDIM  256
#define NPTS  1024
#define NQ    (BATCH * NPTS)
#define KOUT  9

// Scratch
__device__ float g_d2[(size_t)BATCH * NPTS * NPTS];                       // 256MB
__device__ float g_sq[NQ];
__device__ __align__(256) __nv_bfloat16 g_hi[(size_t)BATCH * NPTS * CDIM]; // 32MB [b][n][c]
__device__ __align__(256) __nv_bfloat16 g_lo[(size_t)BATCH * NPTS * CDIM]; // 32MB [b][n][c]

__device__ __forceinline__ uint32_t smem_u32(const void* p) {
    uint32_t a;
    asm("{ .reg .u64 t; cvta.to.shared.u64 t, %1; cvt.u32.u64 %0, t; }" : "=r"(a) : "l"(p));
    return a;
}
#define SW128(o) ((o) ^ (((o) >> 3) & 0x70))

// ---------------------------------------------------------------------------
// Kernel A: squared norms (fp32 exact, from original x)
// ---------------------------------------------------------------------------
__global__ void sqnorm_kernel(const float* __restrict__ x) {
    int g = blockIdx.x * blockDim.x + threadIdx.x;
    int b = g >> 10;
    int n = g & (NPTS - 1);
    const float* xb = x + (size_t)b * CDIM * NPTS + n;
    float s = 0.0f;
    #pragma unroll 8
    for (int c = 0; c < CDIM; c++) {
        float v = xb[(size_t)c * NPTS];
        s = fmaf(v, v, s);
    }
    g_sq[g] = s;
}

// ---------------------------------------------------------------------------
// Kernel B: transpose + bf16 hi/lo split.  x (B,C,N) -> g_hi/g_lo (B,N,C)
// ---------------------------------------------------------------------------
__global__ void prep_kernel(const float* __restrict__ x) {
    __shared__ float T[32][33];
    int b  = blockIdx.z;
    int c0 = blockIdx.y * 32;
    int n0 = blockIdx.x * 32;
    int tx = threadIdx.x, ty = threadIdx.y;   // (32, 8)
    const float* xb = x + (size_t)b * CDIM * NPTS;

    #pragma unroll
    for (int i = 0; i < 4; i++)
        T[ty + 8 * i][tx] = xb[(size_t)(c0 + ty + 8 * i) * NPTS + n0 + tx];
    __syncthreads();

    #pragma unroll
    for (int i = 0; i < 4; i++) {
        float v = T[tx][ty + 8 * i];
        __nv_bfloat16 hi = __float2bfloat16(v);
        __nv_bfloat16 lo = __float2bfloat16(v - __bfloat162float(hi));
        size_t o = ((size_t)(b * NPTS + n0 + ty + 8 * i) << 8) + c0 + tx;
        g_hi[o] = hi;
        g_lo[o] = lo;
    }
}

// ---------------------------------------------------------------------------
// Kernel C: mma.sync bf16 NT-GEMM -> d2 (symmetric 128x128 tiles).
// K-loop: 12 chunks of 64 (3 terms x 256): G = hi.hi + hi.lo + lo.hi
// d2 = sq[r] + sq[c] - 2G.  cp.async double buffer, SW128 SMEM.
// 8 warps: wm = wid&3 (rows 32*wm), wn = wid>>2 (cols 64*wn).
// ---------------------------------------------------------------------------
#define DYN_SMEM 66560   // max(gemm 64KB, epilogue 8*32*65*4 = 66560)

__device__ __forceinline__ void load_chunk(const __nv_bfloat16* A,
                                           const __nv_bfloat16* B,
                                           int m0, int n0, int k0,
                                           uint32_t sbase, int buf, int tid) {
    uint64_t ga, gb;
    asm("cvta.to.global.u64 %0, %1;" : "=l"(ga) : "l"(A));
    asm("cvta.to.global.u64 %0, %1;" : "=l"(gb) : "l"(B));
    uint32_t abase = sbase + buf * 16384;
    uint32_t bbase = sbase + 32768 + buf * 16384;
    #pragma unroll
    for (int i = 0; i < 4; i++) {
        int z = tid + (i << 8);
        int r = z >> 3, j = z & 7;
        uint64_t src = ga + (((size_t)(m0 + r) << 8) + k0 + j * 8) * 2;
        uint32_t dst = abase + SW128((uint32_t)(r * 128 + j * 16));
        asm volatile("cp.async.cg.shared.global [%0], [%1], 16;" :: "r"(dst), "l"(src));
    }
    #pragma unroll
    for (int i = 0; i < 4; i++) {
        int z = tid + (i << 8);
        int r = z >> 3, j = z & 7;
        uint64_t src = gb + (((size_t)(n0 + r) << 8) + k0 + j * 8) * 2;
        uint32_t dst = bbase + SW128((uint32_t)(r * 128 + j * 16));
        asm volatile("cp.async.cg.shared.global [%0], [%1], 16;" :: "r"(dst), "l"(src));
    }
    asm volatile("cp.async.commit_group;" ::: "memory");
}

__global__ void __launch_bounds__(256, 2) gemm_mma_kernel() {
    extern __shared__ char sm[];
    uint32_t sbase = smem_u32(sm);

    int tid = threadIdx.x;
    int wid = tid >> 5;
    int lane = tid & 31;
    int b = blockIdx.y;
    int p = blockIdx.x;          // 0..35 upper-tri tile pair
    int ti = 0, tj = 0;
    {
        int acc = 0;
        #pragma unroll
        for (int i = 0; i < 8; i++) {
            int cnt = 8 - i;
            if (p < acc + cnt) { ti = i; tj = i + (p - acc); break; }
            acc += cnt;
        }
    }
    int m0 = ti * 128, n0 = tj * 128;
    int wm = wid & 3, wn = wid >> 2;

    const __nv_bfloat16* hi = g_hi + ((size_t)b << 18);
    const __nv_bfloat16* lo = g_lo + ((size_t)b << 18);

    float c[2][8][4];
    #pragma unroll
    for (int mt = 0; mt < 2; mt++)
        #pragma unroll
        for (int j = 0; j < 8; j++)
            #pragma unroll
            for (int q = 0; q < 4; q++) c[mt][j][q] = 0.0f;

    // per-lane ldmatrix address components
    int rowA = wm * 32 + (lane & 7) + (lane & 8);        // + mt*16
    int kbA  = (lane & 16);                              // 0 / 16 bytes
    int rowB = wn * 64 + (lane & 7) + ((lane & 16) >> 1);// + ng*16
    int kbB  = (lane & 8) << 1;                          // 0 / 16 bytes

    // chunk ch -> term, k0, operand pointers
    auto term_ptrs = [&](int ch, const __nv_bfloat16*& A, const __nv_bfloat16*& B, int& k0) {
        int term = ch >> 2;
        k0 = (ch & 3) * 64;
        A = (term == 2) ? lo : hi;
        B = (term == 1) ? lo : hi;
    };

    {
        const __nv_bfloat16 *A, *B; int k0;
        term_ptrs(0, A, B, k0);
        load_chunk(A, B, m0, n0, k0, sbase, 0, tid);
    }

    for (int ch = 0; ch < 12; ch++) {
        if (ch + 1 < 12) {
            const __nv_bfloat16 *A, *B; int k0;
            term_ptrs(ch + 1, A, B, k0);
            load_chunk(A, B, m0, n0, k0, sbase, (ch + 1) & 1, tid);
            asm volatile("cp.async.wait_group 1;" ::: "memory");
        } else {
            asm volatile("cp.async.wait_group 0;" ::: "memory");
        }
        __syncthreads();

        int buf = ch & 1;
        uint32_t abase = sbase + buf * 16384;
        uint32_t bbase = sbase + 32768 + buf * 16384;

        #pragma unroll
        for (int kt = 0; kt < 4; kt++) {
            uint32_t a[2][4];
            #pragma unroll
            for (int mt = 0; mt < 2; mt++) {
                uint32_t addr = abase + SW128((uint32_t)((rowA + mt * 16) * 128 + kt * 32 + kbA));
                asm volatile("ldmatrix.sync.aligned.m8n8.x4.shared.b16 {%0,%1,%2,%3}, [%4];"
                             : "=r"(a[mt][0]), "=r"(a[mt][1]), "=r"(a[mt][2]), "=r"(a[mt][3])
                             : "r"(addr));
            }
            uint32_t bf[4][4];
            #pragma unroll
            for (int ng = 0; ng < 4; ng++) {
                uint32_t addr = bbase + SW128((uint32_t)((rowB + ng * 16) * 128 + kt * 32 + kbB));
                asm volatile("ldmatrix.sync.aligned.m8n8.x4.shared.b16 {%0,%1,%2,%3}, [%4];"
                             : "=r"(bf[ng][0]), "=r"(bf[ng][1]), "=r"(bf[ng][2]), "=r"(bf[ng][3])
                             : "r"(addr));
            }
            #pragma unroll
            for (int mt = 0; mt < 2; mt++)
                #pragma unroll
                for (int j = 0; j < 8; j++) {
                    uint32_t b0 = bf[j >> 1][(j & 1) * 2];
                    uint32_t b1 = bf[j >> 1][(j & 1) * 2 + 1];
                    asm volatile(
                        "mma.sync.aligned.m16n8k16.row.col.f32.bf16.bf16.f32 "
                        "{%0,%1,%2,%3}, {%4,%5,%6,%7}, {%8,%9}, {%0,%1,%2,%3};"
                        : "+f"(c[mt][j][0]), "+f"(c[mt][j][1]),
                          "+f"(c[mt][j][2]), "+f"(c[mt][j][3])
                        : "r"(a[mt][0]), "r"(a[mt][1]), "r"(a[mt][2]), "r"(a[mt][3]),
                          "r"(b0), "r"(b1));
                }
        }
        __syncthreads();
    }

    // ---- epilogue: stage per-warp 32x64 accum in SMEM (pad 65), coalesced out
    float* S = (float*)sm + wid * (32 * 65);
    int g = lane >> 2, t4 = lane & 3;
    #pragma unroll
    for (int mt = 0; mt < 2; mt++)
        #pragma unroll
        for (int j = 0; j < 8; j++) {
            int rr = mt * 16 + g, cc = j * 8 + t4 * 2;
            S[rr * 65 + cc]           = c[mt][j][0];
            S[rr * 65 + cc + 1]       = c[mt][j][1];
            S[(rr + 8) * 65 + cc]     = c[mt][j][2];
            S[(rr + 8) * 65 + cc + 1] = c[mt][j][3];
        }
    __syncwarp();

    const float* sqb = g_sq + (b << 10);
    float* dbase = g_d2 + ((size_t)b << 20);
    int mg = m0 + wm * 32, ng = n0 + wn * 64;

    float sqn0 = sqb[ng + lane];
    float sqn1 = sqb[ng + 32 + lane];
    #pragma unroll 4
    for (int r = 0; r < 32; r++) {
        float sq_m = sqb[mg + r];
        float* drow = dbase + (size_t)(mg + r) * NPTS + ng;
        drow[lane]      = sq_m + sqn0 - 2.0f * S[r * 65 + lane];
        drow[32 + lane] = sq_m + sqn1 - 2.0f * S[r * 65 + 32 + lane];
    }

    if (ti != tj) {
        float sq_ml = sqb[mg + lane];
        #pragma unroll 4
        for (int cix = 0; cix < 64; cix++) {
            float sq_n = sqb[ng + cix];
            dbase[(size_t)(ng + cix) * NPTS + mg + lane] =
                sq_n + sq_ml - 2.0f * S[lane * 65 + cix];
        }
    }
}

// ---------------------------------------------------------------------------
// Kernel D: per-query top-(8*dil+1) selection (unchanged, validated)
// ---------------------------------------------------------------------------
__global__ void select_knn_kernel(const int* __restrict__ layer_idx,
                                  float* __restrict__ out, int half) {
    int warp = (blockIdx.x * blockDim.x + threadIdx.x) >> 5;
    int lane = threadIdx.x & 31;
    if (warp >= NQ) return;

    int li = layer_idx[0];
    int dil = li / 4 + 1;
    if (dil > 3) dil = 3;
    if (dil < 1) dil = 1;
    int iters = 8 * dil + 1;

    const float* row = g_d2 + ((size_t)warp << 10);

    float v[32];
    #pragma unroll
    for (int i = 0; i < 8; i++) {
        float4 t = *(const float4*)(row + i * 128 + lane * 4);
        v[i * 4 + 0] = t.x; v[i * 4 + 1] = t.y;
        v[i * 4 + 2] = t.z; v[i * 4 + 3] = t.w;
    }

    float bv = v[0];
    int bs = 0;
    #pragma unroll
    for (int s = 1; s < 32; s++)
        if (v[s] < bv) { bv = v[s]; bs = s; }

    int b = warp >> 10;
    int outbase = warp * KOUT;

    for (int r = 0; r < iters; r++) {
        float wv = bv;
        int wm = ((bs >> 2) << 7) + (lane << 2) + (bs & 3);
        #pragma unroll
        for (int o = 16; o > 0; o >>= 1) {
            float ov = __shfl_xor_sync(0xffffffffu, wv, o);
            int om = __shfl_xor_sync(0xffffffffu, wm, o);
            if (ov < wv || (ov == wv && om < wm)) { wv = ov; wm = om; }
        }

        if ((r % dil) == 0 && lane == 0) {
            int oi = outbase + r / dil;
            if (oi < half) {
                out[oi] = (float)((b << 10) + wm);
                out[half + oi] = (float)warp;
            }
        }

        int owner = (wm >> 2) & 31;
        if (lane == owner) {
            int s = ((wm >> 7) << 2) + (wm & 3);
            #pragma unroll
            for (int ss = 0; ss < 32; ss++)
                if (ss == s) v[ss] = 1e30f;
            bv = v[0]; bs = 0;
            #pragma unroll
            for (int ss = 1; ss < 32; ss++)
                if (v[ss] < bv) { bv = v[ss]; bs = ss; }
        }
    }
}

// ---------------------------------------------------------------------------
// Launch — inputs identified BY SIZE (x = 16,777,216 elems; layer_idx = 1)
// ---------------------------------------------------------------------------
extern "C" void kernel_launch(void* const* d_in, const int* in_sizes, int n_in,
                              void* d_out, int out_size) {
    int xi = 0, li = 1;
    if (n_in >= 2) {
        if (in_sizes[0] >= in_sizes[1]) { xi = 0; li = 1; }
        else                            { xi = 1; li = 0; }
    } else { xi = 0; li = 0; }

    const float* x = (const float*)d_in[xi];
    const int* layer_idx = (const int*)d_in[li];
    float* out = (float*)d_out;
    int half = out_size / 2;

    cudaFuncSetAttribute(gemm_mma_kernel,
                         cudaFuncAttributeMaxDynamicSharedMemorySize, DYN_SMEM);

    sqnorm_kernel<<<NQ / 256, 256>>>(x);

    dim3 pg(32, 8, 64);
    prep_kernel<<<pg, dim3(32, 8)>>>(x);

    dim3 gg(36, BATCH);
    gemm_mma_kernel<<<gg, 256, DYN_SMEM>>>();

    select_knn_kernel<<<NQ / 8, 256>>>(layer_idx, out, half);
}

// round 6
// speedup vs baseline: 3.2286x; 2.4170x over previous
#include <cuda_runtime.h>
#include <cuda_bf16.h>
#include <cstdint>

// Problem constants (fixed by setup_inputs)
#define BATCH 64
#define CDIM  256
#define NPTS  1024
#define NQ    (BATCH * NPTS)
#define KOUT  9

// Scratch
__device__ float g_d2[(size_t)BATCH * NPTS * NPTS];                       // 256MB
__device__ float g_sq[NQ];
__device__ __align__(256) __nv_bfloat16 g_hi[(size_t)BATCH * NPTS * CDIM]; // 32MB [b][n][c]
__device__ __align__(256) __nv_bfloat16 g_lo[(size_t)BATCH * NPTS * CDIM]; // 32MB [b][n][c]

__device__ __forceinline__ uint32_t smem_u32(const void* p) {
    uint32_t a;
    asm("{ .reg .u64 t; cvta.to.shared.u64 t, %1; cvt.u32.u64 %0, t; }" : "=r"(a) : "l"(p));
    return a;
}
#define SW128(o) ((o) ^ (((o) >> 3) & 0x70))

// ---------------------------------------------------------------------------
// Kernel A: squared norms (fp32 exact, from original x)
// ---------------------------------------------------------------------------
__global__ void sqnorm_kernel(const float* __restrict__ x) {
    int g = blockIdx.x * blockDim.x + threadIdx.x;
    int b = g >> 10;
    int n = g & (NPTS - 1);
    const float* xb = x + (size_t)b * CDIM * NPTS + n;
    float s = 0.0f;
    #pragma unroll 8
    for (int c = 0; c < CDIM; c++) {
        float v = xb[(size_t)c * NPTS];
        s = fmaf(v, v, s);
    }
    g_sq[g] = s;
}

// ---------------------------------------------------------------------------
// Kernel B: transpose + bf16 hi/lo split.  x (B,C,N) -> g_hi/g_lo (B,N,C)
// ---------------------------------------------------------------------------
__global__ void prep_kernel(const float* __restrict__ x) {
    __shared__ float T[32][33];
    int b  = blockIdx.z;
    int c0 = blockIdx.y * 32;
    int n0 = blockIdx.x * 32;
    int tx = threadIdx.x, ty = threadIdx.y;   // (32, 8)
    const float* xb = x + (size_t)b * CDIM * NPTS;

    #pragma unroll
    for (int i = 0; i < 4; i++)
        T[ty + 8 * i][tx] = xb[(size_t)(c0 + ty + 8 * i) * NPTS + n0 + tx];
    __syncthreads();

    #pragma unroll
    for (int i = 0; i < 4; i++) {
        float v = T[tx][ty + 8 * i];
        __nv_bfloat16 hi = __float2bfloat16(v);
        __nv_bfloat16 lo = __float2bfloat16(v - __bfloat162float(hi));
        size_t o = ((size_t)(b * NPTS + n0 + ty + 8 * i) << 8) + c0 + tx;
        g_hi[o] = hi;
        g_lo[o] = lo;
    }
}

// ---------------------------------------------------------------------------
// Kernel C: mma.sync bf16 NT-GEMM -> d2 (symmetric 128x128 tiles).
// (unchanged from round 5: PASS, ~160us)
// ---------------------------------------------------------------------------
#define DYN_SMEM 66560

__device__ __forceinline__ void load_chunk(const __nv_bfloat16* A,
                                           const __nv_bfloat16* B,
                                           int m0, int n0, int k0,
                                           uint32_t sbase, int buf, int tid) {
    uint64_t ga, gb;
    asm("cvta.to.global.u64 %0, %1;" : "=l"(ga) : "l"(A));
    asm("cvta.to.global.u64 %0, %1;" : "=l"(gb) : "l"(B));
    uint32_t abase = sbase + buf * 16384;
    uint32_t bbase = sbase + 32768 + buf * 16384;
    #pragma unroll
    for (int i = 0; i < 4; i++) {
        int z = tid + (i << 8);
        int r = z >> 3, j = z & 7;
        uint64_t src = ga + (((size_t)(m0 + r) << 8) + k0 + j * 8) * 2;
        uint32_t dst = abase + SW128((uint32_t)(r * 128 + j * 16));
        asm volatile("cp.async.cg.shared.global [%0], [%1], 16;" :: "r"(dst), "l"(src));
    }
    #pragma unroll
    for (int i = 0; i < 4; i++) {
        int z = tid + (i << 8);
        int r = z >> 3, j = z & 7;
        uint64_t src = gb + (((size_t)(n0 + r) << 8) + k0 + j * 8) * 2;
        uint32_t dst = bbase + SW128((uint32_t)(r * 128 + j * 16));
        asm volatile("cp.async.cg.shared.global [%0], [%1], 16;" :: "r"(dst), "l"(src));
    }
    asm volatile("cp.async.commit_group;" ::: "memory");
}

__global__ void __launch_bounds__(256, 2) gemm_mma_kernel() {
    extern __shared__ char sm[];
    uint32_t sbase = smem_u32(sm);

    int tid = threadIdx.x;
    int wid = tid >> 5;
    int lane = tid & 31;
    int b = blockIdx.y;
    int p = blockIdx.x;
    int ti = 0, tj = 0;
    {
        int acc = 0;
        #pragma unroll
        for (int i = 0; i < 8; i++) {
            int cnt = 8 - i;
            if (p < acc + cnt) { ti = i; tj = i + (p - acc); break; }
            acc += cnt;
        }
    }
    int m0 = ti * 128, n0 = tj * 128;
    int wm = wid & 3, wn = wid >> 2;

    const __nv_bfloat16* hi = g_hi + ((size_t)b << 18);
    const __nv_bfloat16* lo = g_lo + ((size_t)b << 18);

    float c[2][8][4];
    #pragma unroll
    for (int mt = 0; mt < 2; mt++)
        #pragma unroll
        for (int j = 0; j < 8; j++)
            #pragma unroll
            for (int q = 0; q < 4; q++) c[mt][j][q] = 0.0f;

    int rowA = wm * 32 + (lane & 7) + (lane & 8);
    int kbA  = (lane & 16);
    int rowB = wn * 64 + (lane & 7) + ((lane & 16) >> 1);
    int kbB  = (lane & 8) << 1;

    auto term_ptrs = [&](int ch, const __nv_bfloat16*& A, const __nv_bfloat16*& B, int& k0) {
        int term = ch >> 2;
        k0 = (ch & 3) * 64;
        A = (term == 2) ? lo : hi;
        B = (term == 1) ? lo : hi;
    };

    {
        const __nv_bfloat16 *A, *B; int k0;
        term_ptrs(0, A, B, k0);
        load_chunk(A, B, m0, n0, k0, sbase, 0, tid);
    }

    for (int ch = 0; ch < 12; ch++) {
        if (ch + 1 < 12) {
            const __nv_bfloat16 *A, *B; int k0;
            term_ptrs(ch + 1, A, B, k0);
            load_chunk(A, B, m0, n0, k0, sbase, (ch + 1) & 1, tid);
            asm volatile("cp.async.wait_group 1;" ::: "memory");
        } else {
            asm volatile("cp.async.wait_group 0;" ::: "memory");
        }
        __syncthreads();

        int buf = ch & 1;
        uint32_t abase = sbase + buf * 16384;
        uint32_t bbase = sbase + 32768 + buf * 16384;

        #pragma unroll
        for (int kt = 0; kt < 4; kt++) {
            uint32_t a[2][4];
            #pragma unroll
            for (int mt = 0; mt < 2; mt++) {
                uint32_t addr = abase + SW128((uint32_t)((rowA + mt * 16) * 128 + kt * 32 + kbA));
                asm volatile("ldmatrix.sync.aligned.m8n8.x4.shared.b16 {%0,%1,%2,%3}, [%4];"
                             : "=r"(a[mt][0]), "=r"(a[mt][1]), "=r"(a[mt][2]), "=r"(a[mt][3])
                             : "r"(addr));
            }
            uint32_t bf[4][4];
            #pragma unroll
            for (int ng = 0; ng < 4; ng++) {
                uint32_t addr = bbase + SW128((uint32_t)((rowB + ng * 16) * 128 + kt * 32 + kbB));
                asm volatile("ldmatrix.sync.aligned.m8n8.x4.shared.b16 {%0,%1,%2,%3}, [%4];"
                             : "=r"(bf[ng][0]), "=r"(bf[ng][1]), "=r"(bf[ng][2]), "=r"(bf[ng][3])
                             : "r"(addr));
            }
            #pragma unroll
            for (int mt = 0; mt < 2; mt++)
                #pragma unroll
                for (int j = 0; j < 8; j++) {
                    uint32_t b0 = bf[j >> 1][(j & 1) * 2];
                    uint32_t b1 = bf[j >> 1][(j & 1) * 2 + 1];
                    asm volatile(
                        "mma.sync.aligned.m16n8k16.row.col.f32.bf16.bf16.f32 "
                        "{%0,%1,%2,%3}, {%4,%5,%6,%7}, {%8,%9}, {%0,%1,%2,%3};"
                        : "+f"(c[mt][j][0]), "+f"(c[mt][j][1]),
                          "+f"(c[mt][j][2]), "+f"(c[mt][j][3])
                        : "r"(a[mt][0]), "r"(a[mt][1]), "r"(a[mt][2]), "r"(a[mt][3]),
                          "r"(b0), "r"(b1));
                }
        }
        __syncthreads();
    }

    float* S = (float*)sm + wid * (32 * 65);
    int g = lane >> 2, t4 = lane & 3;
    #pragma unroll
    for (int mt = 0; mt < 2; mt++)
        #pragma unroll
        for (int j = 0; j < 8; j++) {
            int rr = mt * 16 + g, cc = j * 8 + t4 * 2;
            S[rr * 65 + cc]           = c[mt][j][0];
            S[rr * 65 + cc + 1]       = c[mt][j][1];
            S[(rr + 8) * 65 + cc]     = c[mt][j][2];
            S[(rr + 8) * 65 + cc + 1] = c[mt][j][3];
        }
    __syncwarp();

    const float* sqb = g_sq + (b << 10);
    float* dbase = g_d2 + ((size_t)b << 20);
    int mg = m0 + wm * 32, ng = n0 + wn * 64;

    float sqn0 = sqb[ng + lane];
    float sqn1 = sqb[ng + 32 + lane];
    #pragma unroll 4
    for (int r = 0; r < 32; r++) {
        float sq_m = sqb[mg + r];
        float* drow = dbase + (size_t)(mg + r) * NPTS + ng;
        drow[lane]      = sq_m + sqn0 - 2.0f * S[r * 65 + lane];
        drow[32 + lane] = sq_m + sqn1 - 2.0f * S[r * 65 + 32 + lane];
    }

    if (ti != tj) {
        float sq_ml = sqb[mg + lane];
        #pragma unroll 4
        for (int cix = 0; cix < 64; cix++) {
            float sq_n = sqb[ng + cix];
            dbase[(size_t)(ng + cix) * NPTS + mg + lane] =
                sq_n + sq_ml - 2.0f * S[lane * 65 + cix];
        }
    }
}

// ---------------------------------------------------------------------------
// Kernel D: per-query selection, threshold + compaction + bitonic (exact).
// One warp per query. Candidate m = i*128 + lane*4 + j for slot s=i*4+j.
// ---------------------------------------------------------------------------
#define FULL 0xffffffffu

__global__ void __launch_bounds__(256, 4) select_knn_kernel(
        const int* __restrict__ layer_idx, float* __restrict__ out, int half) {
    __shared__ uint64_t buf[8][64];

    int warp = (blockIdx.x * blockDim.x + threadIdx.x) >> 5;
    int lane = threadIdx.x & 31;
    int w = (threadIdx.x >> 5);
    if (warp >= NQ) return;

    int li = layer_idx[0];
    int dil = li / 4 + 1;
    if (dil > 3) dil = 3;
    if (dil < 1) dil = 1;

    const float* row = g_d2 + ((size_t)warp << 10);

    // load + order-preserving transform: uint ascending == float ascending
    uint32_t u[32];
    #pragma unroll
    for (int i = 0; i < 8; i++) {
        float4 t = *(const float4*)(row + i * 128 + lane * 4);
        uint32_t a0 = __float_as_uint(t.x), a1 = __float_as_uint(t.y);
        uint32_t a2 = __float_as_uint(t.z), a3 = __float_as_uint(t.w);
        u[i * 4 + 0] = (a0 & 0x80000000u) ? ~a0 : (a0 | 0x80000000u);
        u[i * 4 + 1] = (a1 & 0x80000000u) ? ~a1 : (a1 | 0x80000000u);
        u[i * 4 + 2] = (a2 & 0x80000000u) ? ~a2 : (a2 | 0x80000000u);
        u[i * 4 + 3] = (a3 & 0x80000000u) ? ~a3 : (a3 | 0x80000000u);
    }

    // phase 1: per-lane min
    uint32_t lmin = u[0];
    #pragma unroll
    for (int s = 1; s < 32; s++) lmin = min(lmin, u[s]);

    // phase 2: bitonic sort 32 lane minima; T = 25th smallest (lane 24)
    uint32_t sv = lmin;
    #pragma unroll
    for (int k = 2; k <= 32; k <<= 1) {
        #pragma unroll
        for (int j = k >> 1; j > 0; j >>= 1) {
            uint32_t o = __shfl_xor_sync(FULL, sv, j);
            bool up = ((lane & k) == 0) || (k == 32);
            bool lower = ((lane & j) == 0);
            uint32_t mn = min(sv, o), mx = max(sv, o);
            sv = (up == lower) ? mn : mx;
        }
    }
    uint32_t T = __shfl_sync(FULL, sv, 24);

    // phase 3: count candidates <= T, exclusive scan
    int cnt = 0;
    #pragma unroll
    for (int s = 0; s < 32; s++) cnt += (u[s] <= T);
    int inc = cnt;
    #pragma unroll
    for (int j = 1; j < 32; j <<= 1) {
        int n = __shfl_up_sync(FULL, inc, j);
        if (lane >= j) inc += n;
    }
    int excl = inc - cnt;
    int C = __shfl_sync(FULL, inc, 31);

    int b = warp >> 10;
    int outbase = warp * KOUT;

    if (C <= 64) {
        // compact into smem buffer as (key<<32 | m)
        int pos = excl;
        #pragma unroll
        for (int s = 0; s < 32; s++) {
            if (u[s] <= T) {
                int m = ((s >> 2) << 7) + (lane << 2) + (s & 3);
                buf[w][pos] = ((uint64_t)u[s] << 32) | (uint32_t)m;
                pos++;
            }
        }
        __syncwarp();

        uint64_t x0 = (lane < C)      ? buf[w][lane]      : 0xFFFFFFFFFFFFFFFFull;
        uint64_t x1 = (lane + 32 < C) ? buf[w][lane + 32] : 0xFFFFFFFFFFFFFFFFull;

        // bitonic sort of 64 (virtual index v = slot*32 + lane)
        #pragma unroll
        for (int k = 2; k <= 64; k <<= 1) {
            #pragma unroll
            for (int j = k >> 1; j > 0; j >>= 1) {
                if (j == 32) {
                    uint64_t mn = x0 < x1 ? x0 : x1;
                    uint64_t mx = x0 < x1 ? x1 : x0;
                    x0 = mn; x1 = mx;
                } else {
                    bool lower = ((lane & j) == 0);
                    bool up0, up1;
                    if (k == 64)      { up0 = true;  up1 = true;  }
                    else if (k == 32) { up0 = true;  up1 = false; }
                    else { up0 = up1 = ((lane & k) == 0); }
                    uint64_t o0 = __shfl_xor_sync(FULL, x0, j);
                    uint64_t o1 = __shfl_xor_sync(FULL, x1, j);
                    x0 = (up0 == lower) ? (x0 < o0 ? x0 : o0) : (x0 > o0 ? x0 : o0);
                    x1 = (up1 == lower) ? (x1 < o1 ? x1 : o1) : (x1 > o1 ? x1 : o1);
                }
            }
        }
        // rank r is at lane r, slot 0 (ranks 0..31)
        if (lane <= 8 * dil && (lane % dil) == 0) {
            int m = (int)(x0 & 0xFFFFFFFFull) & 1023;
            int oi = outbase + lane / dil;
            out[oi] = (float)((b << 10) + m);
            out[half + oi] = (float)warp;
        }
    } else {
        // fallback (rare): extract-min with rescan, exact
        uint32_t bv = u[0];
        int bs = 0;
        #pragma unroll
        for (int s = 1; s < 32; s++)
            if (u[s] < bv) { bv = u[s]; bs = s; }

        int iters = 8 * dil + 1;
        for (int r = 0; r < iters; r++) {
            uint32_t wv = bv;
            int wmm = ((bs >> 2) << 7) + (lane << 2) + (bs & 3);
            #pragma unroll
            for (int o = 16; o > 0; o >>= 1) {
                uint32_t ov = __shfl_xor_sync(FULL, wv, o);
                int om = __shfl_xor_sync(FULL, wmm, o);
                if (ov < wv || (ov == wv && om < wmm)) { wv = ov; wmm = om; }
            }
            if ((r % dil) == 0 && lane == 0) {
                int oi = outbase + r / dil;
                out[oi] = (float)((b << 10) + wmm);
                out[half + oi] = (float)warp;
            }
            int owner = (wmm >> 2) & 31;
            if (lane == owner) {
                int s = ((wmm >> 7) << 2) + (wmm & 3);
                #pragma unroll
                for (int ss = 0; ss < 32; ss++)
                    if (ss == s) u[ss] = 0xFFFFFFFFu;
                bv = u[0]; bs = 0;
                #pragma unroll
                for (int ss = 1; ss < 32; ss++)
                    if (u[ss] < bv) { bv = u[ss]; bs = ss; }
            }
        }
    }
}

// ---------------------------------------------------------------------------
// Launch — inputs identified BY SIZE (x = 16,777,216 elems; layer_idx = 1)
// ---------------------------------------------------------------------------
extern "C" void kernel_launch(void* const* d_in, const int* in_sizes, int n_in,
                              void* d_out, int out_size) {
    int xi = 0, li = 1;
    if (n_in >= 2) {
        if (in_sizes[0] >= in_sizes[1]) { xi = 0; li = 1; }
        else                            { xi = 1; li = 0; }
    } else { xi = 0; li = 0; }

    const float* x = (const float*)d_in[xi];
    const int* layer_idx = (const int*)d_in[li];
    float* out = (float*)d_out;
    int half = out_size / 2;

    cudaFuncSetAttribute(gemm_mma_kernel,
                         cudaFuncAttributeMaxDynamicSharedMemorySize, DYN_SMEM);

    sqnorm_kernel<<<NQ / 256, 256>>>(x);

    dim3 pg(32, 8, 64);
    prep_kernel<<<pg, dim3(32, 8)>>>(x);

    dim3 gg(36, BATCH);
    gemm_mma_kernel<<<gg, 256, DYN_SMEM>>>();

    select_knn_kernel<<<NQ / 8, 256>>>(layer_idx, out, half);
}